// round 2
// baseline (speedup 1.0000x reference)
#include <cuda_runtime.h>
#include <cstdint>

#define Bv 128
#define Nv 512
#define Xv 128
#define Hv 256
#define BN (Bv*Nv)           // 65536
#define GSZ (BN*Hv)          // 16777216 floats per gate buffer

// 6 precomputed gate-input buffers: 0=fg_x 1=ig_x 2=in_x 3=og_x 4=tm1 5=tm2
__device__ float g_pre[6][GSZ];

__device__ __forceinline__ float sigmoidf_(float v) { return 1.0f / (1.0f + __expf(-v)); }

__device__ __forceinline__ uint32_t smem_u32_(const void* p) {
    uint32_t a;
    asm("{ .reg .u64 t; cvta.to.shared.u64 t, %1; cvt.u32.u64 %0, t; }" : "=r"(a) : "l"(p));
    return a;
}

// ---- f32x2 packed-math helpers (sm_100a) ----
__device__ __forceinline__ unsigned long long pack2_(float a) {
    unsigned long long r;
    asm("mov.b64 %0, {%1, %1};" : "=l"(r) : "f"(a));
    return r;
}
__device__ __forceinline__ void ffma2_(unsigned long long& d, unsigned long long a, unsigned long long b) {
    asm("fma.rn.f32x2 %0, %1, %2, %0;" : "+l"(d) : "l"(a), "l"(b));
}
__device__ __forceinline__ float2 unpack2_(unsigned long long v) {
    float lo, hi;
    asm("mov.b64 {%0, %1}, %2;" : "=f"(lo), "=f"(hi) : "l"(v));
    return make_float2(lo, hi);
}
__device__ __forceinline__ float unpack_add_(unsigned long long v) {
    float2 u = unpack2_(v);
    return u.x + u.y;
}

__device__ __forceinline__ void st_cluster_f32(uint32_t saddr, uint32_t rank, float v) {
    asm volatile(
        "{\n\t"
        ".reg .b32 ra;\n\t"
        "mapa.shared::cluster.u32 ra, %0, %1;\n\t"
        "st.shared::cluster.f32 [ra], %2;\n\t"
        "}"
        :: "r"(saddr), "r"(rank), "f"(v) : "memory");
}

#define CLUSTER_SYNC_() do { \
    asm volatile("barrier.cluster.arrive.aligned;" ::: "memory"); \
    asm volatile("barrier.cluster.wait.aligned;"   ::: "memory"); \
} while (0)

// ============================================================================
// Phase 1: precompute all input-dependent gate terms.
// grid (512 bn-tiles, 12 h-tiles), block 256, dyn smem 133120 B.
// Each block: 128 bn rows x 128 h cols of ONE gate.
// Inner loop uses fma.rn.f32x2: pairs along the h dimension (contiguous in the
// transposed weight tile), x value broadcast-packed once per row.
// ============================================================================

#define PC_STEP2(CC, COMP)                                                     \
    {                                                                          \
        const float* wr = ws + (k4 * 4 + CC) * 132 + tcol * 8;                 \
        ulonglong2 b01 = *(const ulonglong2*)(wr);                             \
        ulonglong2 b23 = *(const ulonglong2*)(wr + 4);                         \
        _Pragma("unroll")                                                      \
        for (int i = 0; i < 8; i++) {                                          \
            unsigned long long aa = pack2_(av[i].COMP);                        \
            ffma2_(acc2[i][0], aa, b01.x);                                     \
            ffma2_(acc2[i][1], aa, b01.y);                                     \
            ffma2_(acc2[i][2], aa, b23.x);                                     \
            ffma2_(acc2[i][3], aa, b23.y);                                     \
        }                                                                      \
    }

__global__ void __launch_bounds__(256, 1) precompute_kernel(
    const float* __restrict__ x, const float* __restrict__ tvec,
    const float* __restrict__ fg_w_x, const float* __restrict__ fg_b,
    const float* __restrict__ ig_w_x, const float* __restrict__ ig_b,
    const float* __restrict__ in_w_x, const float* __restrict__ in_b,
    const float* __restrict__ og_w_x, const float* __restrict__ og_b, const float* __restrict__ og_w_t,
    const float* __restrict__ tg1_w_x, const float* __restrict__ tg1_b, const float* __restrict__ tg1_w_t,
    const float* __restrict__ tg2_w_x, const float* __restrict__ tg2_b, const float* __restrict__ tg2_w_t)
{
    extern __shared__ float sm[];
    float* xs = sm;               // [128][128]
    float* ws = sm + 128 * 128;   // [128][132]  (transposed weights, padded)

    const int tid  = threadIdx.x;
    const int bn0  = blockIdx.x * 128;
    const int ht   = blockIdx.y;
    const int gate = ht >> 1;
    const int hl0  = (ht & 1) * 128;

    const float* wptr; const float* bptr; const float* tptr = nullptr;
    switch (gate) {
        case 0:  wptr = fg_w_x;  bptr = fg_b;  break;
        case 1:  wptr = ig_w_x;  bptr = ig_b;  break;
        case 2:  wptr = in_w_x;  bptr = in_b;  break;
        case 3:  wptr = og_w_x;  bptr = og_b;  tptr = og_w_t;  break;
        case 4:  wptr = tg1_w_x; bptr = tg1_b; tptr = tg1_w_t; break;
        default: wptr = tg2_w_x; bptr = tg2_b; tptr = tg2_w_t; break;
    }

    // Load x tile [128 rows][128 k]
    for (int i = tid; i < 4096; i += 256) {
        int row = i >> 5, kq = i & 31;
        *(float4*)(xs + row * 128 + kq * 4) =
            *(const float4*)(x + (size_t)(bn0 + row) * 128 + kq * 4);
    }
    // Load + transpose W tile -> ws[k][h] (row stride 132)
    for (int i = tid; i < 4096; i += 256) {
        int h = i >> 5, kq = i & 31;
        float4 v = *(const float4*)(wptr + (size_t)(hl0 + h) * 128 + kq * 4);
        ws[(kq * 4 + 0) * 132 + h] = v.x;
        ws[(kq * 4 + 1) * 132 + h] = v.y;
        ws[(kq * 4 + 2) * 132 + h] = v.z;
        ws[(kq * 4 + 3) * 132 + h] = v.w;
    }
    __syncthreads();

    const int trow = tid >> 4;   // 0..15
    const int tcol = tid & 15;   // 0..15

    unsigned long long acc2[8][4];
    #pragma unroll
    for (int i = 0; i < 8; i++) {
        #pragma unroll
        for (int q = 0; q < 4; q++) acc2[i][q] = 0ull;
    }

    #pragma unroll 2
    for (int k4 = 0; k4 < 32; ++k4) {
        float4 av[8];
        #pragma unroll
        for (int i = 0; i < 8; i++)
            av[i] = *(const float4*)(xs + (trow * 8 + i) * 128 + k4 * 4);
        PC_STEP2(0, x)
        PC_STEP2(1, y)
        PC_STEP2(2, z)
        PC_STEP2(3, w)
    }

    // Epilogue: biases, t-terms, activations; store to g_pre[gate]
    const int hgbase = hl0 + tcol * 8;
    float bias[8], tw[8];
    #pragma unroll
    for (int jj = 0; jj < 8; jj++) {
        bias[jj] = bptr[hgbase + jj];
        tw[jj]   = (tptr != nullptr) ? tptr[hgbase + jj] : 0.0f;
    }
    float* outg = &g_pre[gate][0];
    #pragma unroll
    for (int i = 0; i < 8; i++) {
        int row = bn0 + trow * 8 + i;
        float tv = (gate >= 3) ? tvec[row] : 0.0f;
        float oo[8];
        #pragma unroll
        for (int q = 0; q < 4; q++) {
            float2 u = unpack2_(acc2[i][q]);
            oo[2 * q]     = u.x;
            oo[2 * q + 1] = u.y;
        }
        float o[8];
        #pragma unroll
        for (int jj = 0; jj < 8; jj++) {
            float v;
            if (gate < 3)       v = oo[jj] + bias[jj];
            else if (gate == 3) v = oo[jj] + tw[jj] * tv + bias[jj];
            else                v = sigmoidf_(oo[jj] + tanhf(tw[jj] * tv) + bias[jj]);
            o[jj] = v;
        }
        float4* dst = (float4*)(outg + (size_t)row * 256 + hgbase);
        dst[0] = make_float4(o[0], o[1], o[2], o[3]);
        dst[1] = make_float4(o[4], o[5], o[6], o[7]);
    }
}

// ============================================================================
// Phase 2: recurrence. 16 clusters of 8 CTAs, 256 threads/CTA.
// Cluster c handles batch rows [8c, 8c+8); CTA rank r owns H-slice [32r, 32r+32).
// Recurrent weights (4 gates x 32 x 256 fp32) live in SMEM for the whole
// kernel, laid out as k-adjacent pairs for fma.rn.f32x2:
//   Wt4[k2*256 + gp*128 + j*4 + gl*2 + p] = W_g[r*32+j][2*k2+p],  g = gp*2+gl
//   (g: 0=ig 1=fg 2=in 3=og)
// Each step: k-split matmul (8 warps x 32 k) -> smem reduction -> gates ->
// DSMEM broadcast of new h slice to all 8 peer CTAs -> cluster.sync.
// dyn smem: Wt4 131072 + hbuf 16384 + red 32768 = 180224 B.
// ============================================================================

__global__ void __cluster_dims__(8, 1, 1) __launch_bounds__(256, 1) lstm_rec_kernel(
    const float* __restrict__ fg_w_c, const float* __restrict__ fg_w_h,
    const float* __restrict__ ig_w_c, const float* __restrict__ ig_w_h,
    const float* __restrict__ in_w_h,
    const float* __restrict__ og_w_cn, const float* __restrict__ og_w_h,
    float* __restrict__ out)
{
    extern __shared__ float sm[];
    float* Wt4 = sm;             // 32768 floats, paired layout (see above)
    float* hbuf = sm + 32768;    // [2 parity][8 b][256 h]
    float* red  = sm + 36864;    // [8 kc][32 slots=g*8+bb][32 j]

    const int tid = threadIdx.x;
    const int r   = blockIdx.x & 7;    // cluster rank (1-D cluster)
    const int grp = blockIdx.x >> 3;   // batch group
    const int j   = tid & 31;          // output column within slice
    const int kb  = tid >> 5;          // dual role: k-chunk (matmul) / batch row (epilogue)
    const int jg  = r * 32 + j;        // global h index
    const int bg  = grp * 8 + kb;      // global batch index

    // Fill paired weight layout
    for (int idx = tid; idx < 32768; idx += 256) {
        int p  = idx & 1;
        int gl = (idx >> 1) & 1;
        int jj = (idx >> 2) & 31;
        int gp = (idx >> 7) & 1;
        int k2 = idx >> 8;
        int g  = gp * 2 + gl;
        const float* W = (g == 0) ? ig_w_h : (g == 1) ? fg_w_h
                       : (g == 2) ? in_w_h : og_w_h;
        Wt4[idx] = W[(size_t)(r * 32 + jj) * 256 + (2 * k2 + p)];
    }
    // Zero both h parity buffers
    for (int idx = tid; idx < 4096; idx += 256) hbuf[idx] = 0.0f;

    const float wc_ig = ig_w_c[jg];
    const float wc_fg = fg_w_c[jg];
    const float wc_og = og_w_cn[jg];

    const uint32_t sbase = smem_u32_(sm);
    __syncthreads();
    CLUSTER_SYNC_();

    float cm = 0.0f, hn = 0.0f;
    int par = 0;
    const size_t rowoff = (size_t)bg * Nv * 256 + jg;

    #pragma unroll 1
    for (int n = 0; n < Nv; ++n) {
        // Prefetch this step's streamed gate-input terms early
        const size_t off = rowoff + (size_t)n * 256;
        float p_fg = __ldcs(&g_pre[0][off]);
        float p_ig = __ldcs(&g_pre[1][off]);
        float p_in = __ldcs(&g_pre[2][off]);
        float p_og = __ldcs(&g_pre[3][off]);
        float p_t1 = __ldcs(&g_pre[4][off]);
        float p_t2 = __ldcs(&g_pre[5][off]);

        // Partial matmul: this warp's k-chunk (32 of 256), output col j,
        // all 8 batch rows, all 4 gates. f32x2 pairs along k.
        unsigned long long aig[8], afg[8], ain[8], aog[8];
        #pragma unroll
        for (int q = 0; q < 8; q++) { aig[q] = 0ull; afg[q] = 0ull; ain[q] = 0ull; aog[q] = 0ull; }

        const float* hc = hbuf + par * 2048;
        const int kbase = kb * 32;                 // k offset of this warp's chunk
        const float* wb = Wt4 + (kb * 16) * 256;   // k2 base of this chunk

        #pragma unroll
        for (int k2 = 0; k2 < 16; k2 += 2) {
            ulonglong2 hv[8];
            #pragma unroll
            for (int bb = 0; bb < 8; bb++)
                hv[bb] = *(const ulonglong2*)(hc + bb * 256 + kbase + 2 * k2);
            #pragma unroll
            for (int s = 0; s < 2; s++) {
                const float* wp = wb + (k2 + s) * 256 + j * 4;
                ulonglong2 wA = *(const ulonglong2*)(wp);        // (ig pair, fg pair)
                ulonglong2 wB = *(const ulonglong2*)(wp + 128);  // (in pair, og pair)
                #pragma unroll
                for (int bb = 0; bb < 8; bb++) {
                    unsigned long long h2 = (s == 0) ? hv[bb].x : hv[bb].y;
                    ffma2_(aig[bb], wA.x, h2);
                    ffma2_(afg[bb], wA.y, h2);
                    ffma2_(ain[bb], wB.x, h2);
                    ffma2_(aog[bb], wB.y, h2);
                }
            }
        }

        // Stash partials: red[kc=kb][g*8+bb][j]  (lanes j contiguous -> conflict-free)
        {
            float* rw = red + (kb * 32) * 32 + j;
            #pragma unroll
            for (int bb = 0; bb < 8; bb++) {
                rw[(bb)      * 32] = unpack_add_(aig[bb]);
                rw[(8  + bb) * 32] = unpack_add_(afg[bb]);
                rw[(16 + bb) * 32] = unpack_add_(ain[bb]);
                rw[(24 + bb) * 32] = unpack_add_(aog[bb]);
            }
        }
        __syncthreads();

        // Reduce over the 8 k-chunks for output element (j, b=kb)
        float s_ig = 0.f, s_fg = 0.f, s_in = 0.f, s_og = 0.f;
        #pragma unroll
        for (int kc = 0; kc < 8; kc++) {
            const float* rr = red + (kc * 32) * 32 + j;
            s_ig += rr[(kb)      * 32];
            s_fg += rr[(8  + kb) * 32];
            s_in += rr[(16 + kb) * 32];
            s_og += rr[(24 + kb) * 32];
        }

        // Gates
        float ig  = sigmoidf_(wc_ig * cm + s_ig + p_ig);
        float fg  = sigmoidf_(wc_fg * cm + s_fg + p_fg);
        float inn = tanhf(s_in + p_in);
        float fc  = fg * cm;
        float gi  = ig * inn;
        float cmh = fc + gi * p_t1;
        cm        = fc + gi * p_t2;
        float og  = sigmoidf_(wc_og * cmh + s_og + p_og);
        hn        = og * tanhf(cmh);

        // Broadcast new h element to next-parity buffer of ALL 8 cluster CTAs
        uint32_t dst = sbase + (uint32_t)(32768 + (par ^ 1) * 2048 + kb * 256 + jg) * 4u;
        #pragma unroll
        for (int rk = 0; rk < 8; rk++) st_cluster_f32(dst, rk, hn);

        CLUSTER_SYNC_();   // release our stores / acquire peers' stores
        par ^= 1;
    }

    // Final outputs: h then cm, each [B,H]
    out[(size_t)bg * 256 + jg]         = hn;
    out[32768 + (size_t)bg * 256 + jg] = cm;
}

// ============================================================================
// Launch
// ============================================================================
extern "C" void kernel_launch(void* const* d_in, const int* in_sizes, int n_in,
                              void* d_out, int out_size)
{
    const float* x       = (const float*)d_in[0];
    const float* t       = (const float*)d_in[1];
    const float* fg_w_c  = (const float*)d_in[2];
    const float* fg_w_h  = (const float*)d_in[3];
    const float* fg_w_x  = (const float*)d_in[4];
    const float* fg_b    = (const float*)d_in[5];
    const float* ig_w_c  = (const float*)d_in[6];
    const float* ig_w_h  = (const float*)d_in[7];
    const float* ig_w_x  = (const float*)d_in[8];
    const float* ig_b    = (const float*)d_in[9];
    const float* in_w_h  = (const float*)d_in[10];
    const float* in_w_x  = (const float*)d_in[11];
    const float* in_b    = (const float*)d_in[12];
    const float* og_w_cn = (const float*)d_in[13];
    const float* og_w_h  = (const float*)d_in[14];
    const float* og_w_x  = (const float*)d_in[15];
    const float* og_b    = (const float*)d_in[16];
    const float* og_w_t  = (const float*)d_in[17];
    const float* tg1_w_x = (const float*)d_in[18];
    const float* tg1_w_t = (const float*)d_in[19];
    const float* tg1_b   = (const float*)d_in[20];
    const float* tg2_w_x = (const float*)d_in[21];
    const float* tg2_w_t = (const float*)d_in[22];
    const float* tg2_b   = (const float*)d_in[23];
    float* out = (float*)d_out;

    cudaFuncSetAttribute(precompute_kernel, cudaFuncAttributeMaxDynamicSharedMemorySize, 133120);
    cudaFuncSetAttribute(lstm_rec_kernel,   cudaFuncAttributeMaxDynamicSharedMemorySize, 180224);

    dim3 gp(512, 12);
    precompute_kernel<<<gp, 256, 133120>>>(
        x, t,
        fg_w_x, fg_b, ig_w_x, ig_b, in_w_x, in_b,
        og_w_x, og_b, og_w_t,
        tg1_w_x, tg1_b, tg1_w_t,
        tg2_w_x, tg2_b, tg2_w_t);

    lstm_rec_kernel<<<128, 256, 180224>>>(
        fg_w_c, fg_w_h, ig_w_c, ig_w_h, in_w_h, og_w_cn, og_w_h, out);
}